// round 16
// baseline (speedup 1.0000x reference)
#include <cuda_runtime.h>
#include <cstdint>
#include <climits>

#define S_ 128
#define T_ 2048
#define P_ 1985
#define THREADS 512
#define GRID 296        // 148 SMs x 2 CTAs, persistent
#define NTASKS 1024     // (sample, half) tasks, 1024 windows each
#define XQS 296         // word stride of shifted int8 copies (296 % 32 == 8)

__device__ unsigned g_ctr;

// IMMA m16n8k32 s8*s8+s32; C-operand carries the quantized -||p_c||^2 term
static __device__ __forceinline__ void imma_init(int d[4],
        uint32_t a0, uint32_t a1, uint32_t a2, uint32_t a3,
        uint32_t b0, uint32_t b1, int c01, int c23) {
    asm volatile("mma.sync.aligned.m16n8k32.row.col.s32.s8.s8.s32 "
        "{%0,%1,%2,%3}, {%4,%5,%6,%7}, {%8,%9}, {%10,%10,%11,%11};"
        : "=r"(d[0]), "=r"(d[1]), "=r"(d[2]), "=r"(d[3])
        : "r"(a0), "r"(a1), "r"(a2), "r"(a3), "r"(b0), "r"(b1),
          "r"(c01), "r"(c23));
}
static __device__ __forceinline__ void imma_acc(int d[4],
        uint32_t a0, uint32_t a1, uint32_t a2, uint32_t a3,
        uint32_t b0, uint32_t b1) {
    asm volatile("mma.sync.aligned.m16n8k32.row.col.s32.s8.s8.s32 "
        "{%0,%1,%2,%3}, {%4,%5,%6,%7}, {%8,%9}, {%0,%1,%2,%3};"
        : "+r"(d[0]), "+r"(d[1]), "+r"(d[2]), "+r"(d[3])
        : "r"(a0), "r"(a1), "r"(a2), "r"(a3), "r"(b0), "r"(b1));
}

static __device__ __forceinline__ uint32_t q4pack(float v0, float v1,
                                                  float v2, float v3, float sc) {
    int q0 = __float2int_rn(v0 * sc), q1 = __float2int_rn(v1 * sc);
    int q2 = __float2int_rn(v2 * sc), q3 = __float2int_rn(v3 * sc);
    return (uint32_t)(q0 & 255) | ((uint32_t)(q1 & 255) << 8) |
           ((uint32_t)(q2 & 255) << 16) | ((uint32_t)(q3 & 255) << 24);
}

__global__ void init_kernel(unsigned* __restrict__ outb) {
    int i = blockIdx.x * blockDim.x + threadIdx.x;
    if (i < 512 * S_) outb[i] = 0x7F800000u;   // +inf bits (atomicMin merge)
    if (i == 0) g_ctr = 0u;
}

__global__ void __launch_bounds__(THREADS, 2)
shapelet_imma_kernel(const float* __restrict__ x,
                     const float* __restrict__ sh,
                     float* __restrict__ out) {
    __shared__ float    xr[1160];        // raw x segment, zero-padded
    __shared__ uint32_t xq4[4 * XQS];    // 4 byte-shifted packed int8 copies
    __shared__ uint32_t Bq[128 * 16];    // quantized centered shapelets
    __shared__ int      pcq[1024];       // round(-||p_c||^2 * dx*ds/2)
    __shared__ float    p2f[1024];       // exact ||p_c||^2
    __shared__ float    wsum[1024];      // exact raw window sum
    __shared__ float    smean[S_], s2s[S_];
    __shared__ int      wmaxI[256], win[S_];
    __shared__ float    red[16];
    __shared__ float    sc_ds, sc_u2;    // shapelet scale; 0.5*dx*ds per task
    __shared__ unsigned stsk;

    const int tid = threadIdx.x;
    const int wid = tid >> 5, lane = tid & 31;
    const int gid = lane >> 2, tig = lane & 3;
    unsigned* outb = reinterpret_cast<unsigned*>(out);

    // ===== once per CTA: shapelet stats + global centered-max =====
    float rmax = 0.f;
    if (tid < S_) {
        const float* sp = sh + tid * 64;
        float sm = 0.f, q2 = 0.f;
#pragma unroll
        for (int l = 0; l < 64; ++l) { float v = sp[l]; sm += v; q2 = fmaf(v, v, q2); }
        float mean = sm * (1.f / 64.f);
        smean[tid] = mean; s2s[tid] = q2;
#pragma unroll
        for (int l = 0; l < 64; ++l) rmax = fmaxf(rmax, fabsf(sp[l] - mean));
    }
#pragma unroll
    for (int o = 16; o > 0; o >>= 1) rmax = fmaxf(rmax, __shfl_xor_sync(~0u, rmax, o));
    if (lane == 0) red[wid] = rmax;
    __syncthreads();
    if (tid == 0) {
        float m = red[0];
#pragma unroll
        for (int i = 1; i < 16; ++i) m = fmaxf(m, red[i]);
        sc_ds = 127.f / fmaxf(m, 1e-20f);
    }
    __syncthreads();
    if (tid < S_) {
        const float* sp = sh + tid * 64;
        float mean = smean[tid], ds = sc_ds;
#pragma unroll
        for (int j = 0; j < 16; ++j)
            Bq[tid * 16 + j] = q4pack(sp[4 * j] - mean, sp[4 * j + 1] - mean,
                                      sp[4 * j + 2] - mean, sp[4 * j + 3] - mean, ds);
    }
    __syncthreads();

    // persistent B fragments: 2 n-chunks x 2 k32-chunks x 2 regs
    const int h2 = wid >> 3, q = wid & 7;
    uint32_t Bf[2][2][2];
#pragma unroll
    for (int nc = 0; nc < 2; ++nc) {
        int row = q * 16 + nc * 8 + gid;
#pragma unroll
        for (int kc = 0; kc < 2; ++kc) {
            Bf[nc][kc][0] = Bq[row * 16 + kc * 8 + tig];
            Bf[nc][kc][1] = Bq[row * 16 + kc * 8 + 4 + tig];
        }
    }

    // ===== task loop =====
    for (;;) {
        if (tid == 0) stsk = atomicAdd(&g_ctr, 1u);
        __syncthreads();
        const unsigned task = stsk;
        if (task >= NTASKS) break;
        const int b = (int)(task >> 1), hh = (int)(task & 1);
        const int limW = hh ? (P_ - 1024) : 1024;   // valid local windows
        const int limX = hh ? 1024 : 1160;          // valid floats in segment

        // ---- load x segment, absmax ----
        const float* xg = x + (size_t)b * T_ + hh * 1024;
        float lmax = 0.f;
        for (int i = tid; i < 1160; i += THREADS) {
            float v = (i < limX) ? xg[i] : 0.f;
            xr[i] = v;
            lmax = fmaxf(lmax, fabsf(v));
        }
#pragma unroll
        for (int o = 16; o > 0; o >>= 1) lmax = fmaxf(lmax, __shfl_xor_sync(~0u, lmax, o));
        if (lane == 0) red[wid] = lmax;
        __syncthreads();
        if (tid == 0) {
            float m = red[0];
#pragma unroll
            for (int i = 1; i < 16; ++i) m = fmaxf(m, red[i]);
            float dx = 127.f / fmaxf(m, 1e-20f);
            sc_u2 = 0.5f * dx * sc_ds;
            red[0] = dx;
        }
        __syncthreads();
        const float dxinv = red[0], u2 = sc_u2;

        // ---- 4 byte-shifted quantized copies ----
#pragma unroll
        for (int c = 0; c < 4; ++c)
            for (int i = tid; i < 288; i += THREADS)
                xq4[c * XQS + i] = q4pack(xr[4 * i + c], xr[4 * i + c + 1],
                                          xr[4 * i + c + 2], xr[4 * i + c + 3], dxinv);

        // ---- exact window stats: 2 windows/thread ----
        {
            int p0 = tid * 2;
            float s = 0.f, qq = 0.f;
#pragma unroll
            for (int l = 0; l < 64; ++l) { float v = xr[p0 + l]; s += v; qq = fmaf(v, v, qq); }
            float p2 = fmaf(-s, s * (1.f / 64.f), qq);
            p2f[p0] = p2; wsum[p0] = s; pcq[p0] = __float2int_rn(-p2 * u2);
            float vo = xr[p0], vi = xr[p0 + 64];
            s += vi - vo; qq += fmaf(vi, vi, -vo * vo);
            p2 = fmaf(-s, s * (1.f / 64.f), qq);
            p2f[p0 + 1] = p2; wsum[p0 + 1] = s; pcq[p0 + 1] = __float2int_rn(-p2 * u2);
        }
        __syncthreads();

        // ---- main loop: 32 m-groups; integer score max with window index ----
        int mnv[4] = {INT_MIN, INT_MIN, INT_MIN, INT_MIN};
        const int mstart = h2 * 512;
        const uint32_t* bp = xq4 + XQS * (gid & 3) + (mstart >> 2) + (gid >> 2) + tig;
        int rbase = mstart + gid;
#pragma unroll 4
        for (int mg = 0; mg < 32; ++mg) {
            uint32_t a[8];
#pragma unroll
            for (int j = 0; j < 8; ++j) a[j] = bp[2 * j];
            const int pc0 = pcq[rbase], pc1 = pcq[rbase + 8];
            const bool ok0 = rbase < limW, ok1 = rbase + 8 < limW;

            int A0[4], A1[4];
            imma_init(A0, a[0], a[1], a[2], a[3], Bf[0][0][0], Bf[0][0][1], pc0, pc1);
            imma_init(A1, a[0], a[1], a[2], a[3], Bf[1][0][0], Bf[1][0][1], pc0, pc1);
            imma_acc(A0, a[4], a[5], a[6], a[7], Bf[0][1][0], Bf[0][1][1]);
            imma_acc(A1, a[4], a[5], a[6], a[7], Bf[1][1][0], Bf[1][1][1]);

            int i0 = rbase, i1 = rbase + 8;
            int c00 = ok0 ? A0[0] * 1024 + i0 : INT_MIN;
            int c02 = ok1 ? A0[2] * 1024 + i1 : INT_MIN;
            int c01 = ok0 ? A0[1] * 1024 + i0 : INT_MIN;
            int c03 = ok1 ? A0[3] * 1024 + i1 : INT_MIN;
            int c10 = ok0 ? A1[0] * 1024 + i0 : INT_MIN;
            int c12 = ok1 ? A1[2] * 1024 + i1 : INT_MIN;
            int c11 = ok0 ? A1[1] * 1024 + i0 : INT_MIN;
            int c13 = ok1 ? A1[3] * 1024 + i1 : INT_MIN;
            mnv[0] = max(mnv[0], max(c00, c02));
            mnv[1] = max(mnv[1], max(c01, c03));
            mnv[2] = max(mnv[2], max(c10, c12));
            mnv[3] = max(mnv[3], max(c11, c13));
            bp += 4; rbase += 16;
        }

        // ---- reduce over the 8 row-groups (keeps encoded index) ----
#pragma unroll
        for (int i = 0; i < 4; ++i) {
            int nc = i >> 1, e = i & 1;
            int m = mnv[i];
            m = max(m, __shfl_xor_sync(~0u, m, 4));
            m = max(m, __shfl_xor_sync(~0u, m, 8));
            m = max(m, __shfl_xor_sync(~0u, m, 16));
            if (lane < 4)
                wmaxI[h2 * 128 + q * 16 + nc * 8 + lane * 2 + e] = m;
        }
        __syncthreads();
        if (tid < S_) win[tid] = max(wmaxI[tid], wmaxI[128 + tid]);
        __syncthreads();

        // ---- exact fp32 rescue: winner window +-2 neighbors ----
        {
            const int s = tid >> 2, t = tid & 3;
            const int wstar = win[s] & 1023;
            int wb = wstar - 2;
            wb = wb < 0 ? 0 : wb;
            wb = wb > limW - 5 ? limW - 5 : wb;
            float sraw[16];
            const float* sp = sh + s * 64 + 16 * t;
#pragma unroll
            for (int j = 0; j < 16; ++j) sraw[j] = sp[j];
            float dsum[5];
#pragma unroll
            for (int w = 0; w < 5; ++w) {
                float d = 0.f;
                const float* xw = xr + wb + w + 16 * t;
#pragma unroll
                for (int j = 0; j < 16; ++j) d = fmaf(xw[j], sraw[j], d);
                d += __shfl_xor_sync(~0u, d, 1);
                d += __shfl_xor_sync(~0u, d, 2);
                dsum[w] = d;
            }
            if (t == 0) {
                float mean = smean[s], s2v = s2s[s], best = 3.4e38f;
#pragma unroll
                for (int w = 0; w < 5; ++w) {
                    float dot_c = dsum[w] - mean * wsum[wb + w];
                    float d2 = p2f[wb + w] + s2v - 2.f * dot_c;
                    best = fminf(best, d2);
                }
                float dist = sqrtf(fmaxf(best, 0.f));
                atomicMin(&outb[b * S_ + s], __float_as_uint(dist));
            }
        }
        __syncthreads();   // protect smem before next task
    }
}

extern "C" void kernel_launch(void* const* d_in, const int* in_sizes, int n_in,
                              void* d_out, int out_size) {
    const float* x  = (const float*)d_in[0];   // (512, 1, 2048) fp32
    const float* sh = (const float*)d_in[1];   // (128, 1, 64)   fp32
    float* out = (float*)d_out;                // (512, 128)     fp32
    init_kernel<<<(512 * S_ + 255) / 256, 256>>>((unsigned*)d_out);
    shapelet_imma_kernel<<<GRID, THREADS>>>(x, sh, out);
}